// round 6
// baseline (speedup 1.0000x reference)
#include <cuda_runtime.h>
#include <cuda_bf16.h>

// Problem constants
#define R_REL 8
#define C_CH  4
#define E_EDG 2000000LL
#define RE    (R_REL * E_EDG)          // 16,000,000

// ---------------------------------------------------------------------------
// Single fused kernel, 8 edges per thread.
//  - lanes 0-3 of warp 0: softmax(weight, axis=0) -> smem (redundant/block).
//  - lane 32: int64-vs-int32 detect (ids < 1e5 => high words all zero).
//  - every thread: 6 front-batched 16B loads, 12 16B streaming stores.
// Output layout (float32):
//   [0*RE .. 1*RE)  : (float)edge_index[r, 0, e]  at slot r*E+e
//   [1*RE .. 2*RE)  : (float)edge_index[r, 1, e]
//   [2*RE + c*RE)   : filt[r][c] * edge_value[r, e],  c = 0..3
// ---------------------------------------------------------------------------
__global__ void __launch_bounds__(128) gtconv_fused_kernel(
    const float* __restrict__ weight,
    const void*  __restrict__ edge_index_raw,
    const float* __restrict__ edge_value,
    float* __restrict__ out)
{
    __shared__ float s_filt[R_REL * C_CH];
    __shared__ int   s_is64;

    int t = threadIdx.x;
    if (t < C_CH) {
        float v[R_REL];
        float m = -1e30f;
        #pragma unroll
        for (int r = 0; r < R_REL; r++) {
            v[r] = __ldg(&weight[r * C_CH + t]);
            m = fmaxf(m, v[r]);
        }
        float s = 0.f;
        #pragma unroll
        for (int r = 0; r < R_REL; r++) {
            v[r] = __expf(v[r] - m);
            s += v[r];
        }
        float inv = 1.f / s;
        #pragma unroll
        for (int r = 0; r < R_REL; r++)
            s_filt[r * C_CH + t] = v[r] * inv;
    } else if (t == 32) {
        const unsigned long long* q = (const unsigned long long*)edge_index_raw;
        int is64 = 1;
        #pragma unroll
        for (int i = 0; i < 16; i++)
            if ((__ldg(&q[i]) >> 32) != 0ULL) is64 = 0;
        s_is64 = is64;
    }
    __syncthreads();

    const long long CHUNKS_PER_R = E_EDG / 8;                 // 250,000
    long long tid = (long long)blockIdx.x * blockDim.x + t;   // 2,000,000 total

    int       r = (int)(tid / CHUNKS_PER_R);
    long long e = (tid % CHUNKS_PER_R) * 8;

    const float4 f = *reinterpret_cast<const float4*>(&s_filt[r * C_CH]);

    long long base = (long long)r * E_EDG + e;

    // o0[2]: row-0 index as float, o1[2]: row-1 index as float
    float4 o0[2], o1[2];
    float4 v0, v1;

    if (s_is64) {
        const long long* ei = (const long long*)edge_index_raw;
        const longlong2* p0 = reinterpret_cast<const longlong2*>(ei + (long long)r * 2 * E_EDG + e);
        const longlong2* p1 = reinterpret_cast<const longlong2*>(ei + (long long)r * 2 * E_EDG + E_EDG + e);
        // front-batch all 10 loads
        longlong2 a0 = __ldcs(&p0[0]), a1 = __ldcs(&p0[1]), a2 = __ldcs(&p0[2]), a3 = __ldcs(&p0[3]);
        longlong2 b0 = __ldcs(&p1[0]), b1 = __ldcs(&p1[1]), b2 = __ldcs(&p1[2]), b3 = __ldcs(&p1[3]);
        v0 = __ldcs(reinterpret_cast<const float4*>(edge_value + base));
        v1 = __ldcs(reinterpret_cast<const float4*>(edge_value + base + 4));
        o0[0] = make_float4((float)(int)a0.x, (float)(int)a0.y, (float)(int)a1.x, (float)(int)a1.y);
        o0[1] = make_float4((float)(int)a2.x, (float)(int)a2.y, (float)(int)a3.x, (float)(int)a3.y);
        o1[0] = make_float4((float)(int)b0.x, (float)(int)b0.y, (float)(int)b1.x, (float)(int)b1.y);
        o1[1] = make_float4((float)(int)b2.x, (float)(int)b2.y, (float)(int)b3.x, (float)(int)b3.y);
    } else {
        const int* ei = (const int*)edge_index_raw;
        const int4* p0 = reinterpret_cast<const int4*>(ei + (long long)r * 2 * E_EDG + e);
        const int4* p1 = reinterpret_cast<const int4*>(ei + (long long)r * 2 * E_EDG + E_EDG + e);
        // front-batch all 6 independent loads (MLP_p1 = 6)
        int4 a0 = __ldcs(&p0[0]);
        int4 a1 = __ldcs(&p0[1]);
        int4 b0 = __ldcs(&p1[0]);
        int4 b1 = __ldcs(&p1[1]);
        v0 = __ldcs(reinterpret_cast<const float4*>(edge_value + base));
        v1 = __ldcs(reinterpret_cast<const float4*>(edge_value + base + 4));
        o0[0] = make_float4((float)a0.x, (float)a0.y, (float)a0.z, (float)a0.w);
        o0[1] = make_float4((float)a1.x, (float)a1.y, (float)a1.z, (float)a1.w);
        o1[0] = make_float4((float)b0.x, (float)b0.y, (float)b0.z, (float)b0.w);
        o1[1] = make_float4((float)b1.x, (float)b1.y, (float)b1.z, (float)b1.w);
    }

    // index copies
    __stcs(reinterpret_cast<float4*>(out + base),          o0[0]);
    __stcs(reinterpret_cast<float4*>(out + base + 4),      o0[1]);
    __stcs(reinterpret_cast<float4*>(out + RE + base),     o1[0]);
    __stcs(reinterpret_cast<float4*>(out + RE + base + 4), o1[1]);

    // scaled values: 4 channels x 8 edges
    float* vbase = out + 2 * RE + base;
    __stcs(reinterpret_cast<float4*>(vbase + 0 * RE),
           make_float4(v0.x * f.x, v0.y * f.x, v0.z * f.x, v0.w * f.x));
    __stcs(reinterpret_cast<float4*>(vbase + 0 * RE + 4),
           make_float4(v1.x * f.x, v1.y * f.x, v1.z * f.x, v1.w * f.x));
    __stcs(reinterpret_cast<float4*>(vbase + 1 * RE),
           make_float4(v0.x * f.y, v0.y * f.y, v0.z * f.y, v0.w * f.y));
    __stcs(reinterpret_cast<float4*>(vbase + 1 * RE + 4),
           make_float4(v1.x * f.y, v1.y * f.y, v1.z * f.y, v1.w * f.y));
    __stcs(reinterpret_cast<float4*>(vbase + 2 * RE),
           make_float4(v0.x * f.z, v0.y * f.z, v0.z * f.z, v0.w * f.z));
    __stcs(reinterpret_cast<float4*>(vbase + 2 * RE + 4),
           make_float4(v1.x * f.z, v1.y * f.z, v1.z * f.z, v1.w * f.z));
    __stcs(reinterpret_cast<float4*>(vbase + 3 * RE),
           make_float4(v0.x * f.w, v0.y * f.w, v0.z * f.w, v0.w * f.w));
    __stcs(reinterpret_cast<float4*>(vbase + 3 * RE + 4),
           make_float4(v1.x * f.w, v1.y * f.w, v1.z * f.w, v1.w * f.w));
}

extern "C" void kernel_launch(void* const* d_in, const int* in_sizes, int n_in,
                              void* d_out, int out_size) {
    const float* weight     = (const float*)d_in[0];
    const void*  edge_index = (const void*)d_in[1];
    const float* edge_value = (const float*)d_in[2];
    float* out = (float*)d_out;

    const long long total_chunks = (long long)R_REL * (E_EDG / 8); // 2,000,000
    int threads = 128;
    int blocks  = (int)(total_chunks / threads);                   // 15,625 exact
    gtconv_fused_kernel<<<blocks, threads>>>(weight, edge_index, edge_value, out);
}

// round 7
// speedup vs baseline: 1.2271x; 1.2271x over previous
#include <cuda_runtime.h>
#include <cuda_bf16.h>

// Problem constants
#define R_REL 8
#define C_CH  4
#define E_EDG 2000000LL
#define RE    (R_REL * E_EDG)          // 16,000,000
#define NCHUNK (RE / 4)                // 4,000,000 chunks of 4 edges
#define CHUNKS_PER_R (E_EDG / 4)       // 500,000

// ---------------------------------------------------------------------------
// Single fused kernel. Chunk = 4 consecutive edges (16B), perfectly
// warp-coalesced. Each thread handles TWO chunks: c and c+32 (same warp tile
// of 64 chunks), doubling front-batched MLP (3 -> 6 independent loads) while
// keeping every load/store instruction lane-contiguous (512B per warp).
//  - lanes 0-3: softmax(weight, axis=0) -> smem (redundant per block).
//  - lane 32: int64-vs-int32 detect (ids < 1e5 => high words all zero).
// Output layout (float32):
//   [0*RE .. 1*RE)  : (float)edge_index[r, 0, e]  at slot r*E+e
//   [1*RE .. 2*RE)  : (float)edge_index[r, 1, e]
//   [2*RE + c*RE)   : filt[r][c] * edge_value[r, e],  c = 0..3
// ---------------------------------------------------------------------------
__global__ void __launch_bounds__(128) gtconv_fused_kernel(
    const float* __restrict__ weight,
    const void*  __restrict__ edge_index_raw,
    const float* __restrict__ edge_value,
    float* __restrict__ out)
{
    __shared__ float s_filt[R_REL * C_CH];
    __shared__ int   s_is64;

    int t = threadIdx.x;
    if (t < C_CH) {
        float v[R_REL];
        float m = -1e30f;
        #pragma unroll
        for (int r = 0; r < R_REL; r++) {
            v[r] = __ldg(&weight[r * C_CH + t]);
            m = fmaxf(m, v[r]);
        }
        float s = 0.f;
        #pragma unroll
        for (int r = 0; r < R_REL; r++) {
            v[r] = __expf(v[r] - m);
            s += v[r];
        }
        float inv = 1.f / s;
        #pragma unroll
        for (int r = 0; r < R_REL; r++)
            s_filt[r * C_CH + t] = v[r] * inv;
    } else if (t == 32) {
        const unsigned long long* q = (const unsigned long long*)edge_index_raw;
        int is64 = 1;
        #pragma unroll
        for (int i = 0; i < 16; i++)
            if ((__ldg(&q[i]) >> 32) != 0ULL) is64 = 0;
        s_is64 = is64;
    }
    __syncthreads();

    // warp tile: 64 consecutive chunks; lane handles c0 = tile+lane, c1 = c0+32
    int wid  = t >> 5;
    int lane = t & 31;
    long long c0 = (long long)blockIdx.x * 256 + wid * 64 + lane;  // < 4,000,000
    // chunk -> (relation, edge, bases); the two chunks may differ in relation
    long long cs[2] = {c0, c0 + 32};
    int       rr[2];
    long long ibase[2];   // element offset into edge_value / out streams
    long long eoff0[2];   // element offset of index row0 within edge_index
    #pragma unroll
    for (int i = 0; i < 2; i++) {
        int       r = (int)(cs[i] / CHUNKS_PER_R);
        long long e = (cs[i] % CHUNKS_PER_R) * 4;
        rr[i]    = r;
        ibase[i] = (long long)r * E_EDG + e;
        eoff0[i] = (long long)r * 2 * E_EDG + e;
    }

    float4 o0[2], o1[2], v[2];

    if (s_is64) {
        const long long* ei = (const long long*)edge_index_raw;
        longlong2 a[2][2], b[2][2];
        #pragma unroll
        for (int i = 0; i < 2; i++) {
            const longlong2* p0 = reinterpret_cast<const longlong2*>(ei + eoff0[i]);
            const longlong2* p1 = reinterpret_cast<const longlong2*>(ei + eoff0[i] + E_EDG);
            a[i][0] = __ldcs(&p0[0]); a[i][1] = __ldcs(&p0[1]);
            b[i][0] = __ldcs(&p1[0]); b[i][1] = __ldcs(&p1[1]);
            v[i] = __ldcs(reinterpret_cast<const float4*>(edge_value + ibase[i]));
        }
        #pragma unroll
        for (int i = 0; i < 2; i++) {
            o0[i] = make_float4((float)(int)a[i][0].x, (float)(int)a[i][0].y,
                                (float)(int)a[i][1].x, (float)(int)a[i][1].y);
            o1[i] = make_float4((float)(int)b[i][0].x, (float)(int)b[i][0].y,
                                (float)(int)b[i][1].x, (float)(int)b[i][1].y);
        }
    } else {
        const int* ei = (const int*)edge_index_raw;
        int4 a[2], b[2];
        // 6 independent, fully coalesced front-batched loads
        #pragma unroll
        for (int i = 0; i < 2; i++) {
            a[i] = __ldcs(reinterpret_cast<const int4*>(ei + eoff0[i]));
            b[i] = __ldcs(reinterpret_cast<const int4*>(ei + eoff0[i] + E_EDG));
            v[i] = __ldcs(reinterpret_cast<const float4*>(edge_value + ibase[i]));
        }
        #pragma unroll
        for (int i = 0; i < 2; i++) {
            o0[i] = make_float4((float)a[i].x, (float)a[i].y, (float)a[i].z, (float)a[i].w);
            o1[i] = make_float4((float)b[i].x, (float)b[i].y, (float)b[i].z, (float)b[i].w);
        }
    }

    #pragma unroll
    for (int i = 0; i < 2; i++) {
        const float4 f = *reinterpret_cast<const float4*>(&s_filt[rr[i] * C_CH]);
        long long base = ibase[i];
        __stcs(reinterpret_cast<float4*>(out + base),      o0[i]);
        __stcs(reinterpret_cast<float4*>(out + RE + base), o1[i]);
        float* vbase = out + 2 * RE + base;
        float4 vv = v[i];
        __stcs(reinterpret_cast<float4*>(vbase + 0 * RE),
               make_float4(vv.x * f.x, vv.y * f.x, vv.z * f.x, vv.w * f.x));
        __stcs(reinterpret_cast<float4*>(vbase + 1 * RE),
               make_float4(vv.x * f.y, vv.y * f.y, vv.z * f.y, vv.w * f.y));
        __stcs(reinterpret_cast<float4*>(vbase + 2 * RE),
               make_float4(vv.x * f.z, vv.y * f.z, vv.z * f.z, vv.w * f.z));
        __stcs(reinterpret_cast<float4*>(vbase + 3 * RE),
               make_float4(vv.x * f.w, vv.y * f.w, vv.z * f.w, vv.w * f.w));
    }
}

extern "C" void kernel_launch(void* const* d_in, const int* in_sizes, int n_in,
                              void* d_out, int out_size) {
    const float* weight     = (const float*)d_in[0];
    const void*  edge_index = (const void*)d_in[1];
    const float* edge_value = (const float*)d_in[2];
    float* out = (float*)d_out;

    // 4,000,000 chunks, 256 chunks per 128-thread block -> 15,625 blocks exact
    int threads = 128;
    int blocks  = (int)(NCHUNK / 256);
    gtconv_fused_kernel<<<blocks, threads>>>(weight, edge_index, edge_value, out);
}